// round 7
// baseline (speedup 1.0000x reference)
#include <cuda_runtime.h>
#include <math_constants.h>

// Problem constants (fixed by reference)
constexpr int B = 8;
constexpr int N = 4096;          // == M

// z-strip grid
constexpr int   S    = 200;
constexpr float ZLO  = -5.0f;
constexpr float W    = 0.05f;
constexpr float INVW = 20.0f;

constexpr int QT     = 128;              // search block size
constexpr int QBLK   = N / QT;           // 32 query blocks per (pass,b)
constexpr int TOTALB = QBLK * B * 2;     // 512 search blocks

// Scratch (no allocations allowed)
// g_pts[c][b][i] = (-2x, -2y, -2z, x^2+y^2+z^2), bucketed by z-strip
__device__ float4   g_pts[2][B][N];
__device__ int      g_off[2][B][S + 1];
__device__ float    g_acc[4];            // rowmin-sum, sqrt-sum, colmin-sum, unc-sum
__device__ unsigned g_tick;

// ---------------------------------------------------------------------------
// Bucket kernel: grid (2, B), block 256. Histogram z-strips, prefix, scatter
// transformed points. Block (0,0) also zeroes the accumulators/ticket.
// ---------------------------------------------------------------------------
__global__ void __launch_bounds__(256)
bucket_kernel(const float* __restrict__ pred, const float* __restrict__ targ)
{
    __shared__ int cnt[S];
    __shared__ int start[S];
    __shared__ int cur[S];
    const int c = blockIdx.x, b = blockIdx.y, tid = threadIdx.x;
    const float* src = (c == 0 ? pred : targ) + (size_t)b * N * 3;

    if (c == 0 && b == 0) {
        if (tid < 4) g_acc[tid] = 0.f;
        if (tid == 4) g_tick = 0u;
    }

    for (int s = tid; s < S; s += 256) { cnt[s] = 0; cur[s] = 0; }
    __syncthreads();

    for (int i = tid; i < N; i += 256) {
        const float z = src[i * 3 + 2];
        const int s = min(max((int)((z - ZLO) * INVW), 0), S - 1);
        atomicAdd(&cnt[s], 1);
    }
    __syncthreads();

    if (tid == 0) {
        int acc = 0;
        for (int s = 0; s < S; s++) {
            start[s] = acc;
            g_off[c][b][s] = acc;
            acc += cnt[s];
        }
        g_off[c][b][S] = acc;            // == N
    }
    __syncthreads();

    for (int i = tid; i < N; i += 256) {
        const float x = src[i * 3 + 0];
        const float y = src[i * 3 + 1];
        const float z = src[i * 3 + 2];
        const int s = min(max((int)((z - ZLO) * INVW), 0), S - 1);
        const int pos = start[s] + atomicAdd(&cur[s], 1);
        g_pts[c][b][pos] = make_float4(-2.f * x, -2.f * y, -2.f * z,
                                       x * x + y * y + z * z);
    }
}

// ---------------------------------------------------------------------------
// Search kernel: grid (QBLK, B, 2), block 128. pass 0: queries=pred,
// targets=targ (chamfer row-min + EMD); pass 1: reversed (col-min).
// Per-thread outward strip walk with exact edge-distance pruning:
//   d2_true >= (gap to strip edge)^2  for every point in that strip.
// Tracks partial = t^2 - 2 q.t (min commutes with +qn2). Loop is
// warp-synchronous (__all_sync) so addresses stay near-uniform.
// ---------------------------------------------------------------------------
__global__ void __launch_bounds__(QT)
search_kernel(const float* __restrict__ unc, float* __restrict__ out)
{
    const int tid  = threadIdx.x;
    const int b    = blockIdx.y;
    const int pass = blockIdx.z;
    const int qc   = pass, tc = 1 - pass;
    const int qi   = blockIdx.x * QT + tid;

    const float4 Q  = g_pts[qc][b][qi];
    const float qx  = -0.5f * Q.x;
    const float qy  = -0.5f * Q.y;
    const float qz  = -0.5f * Q.z;
    const float qn2 = Q.w;

    const float4* __restrict__ T  = g_pts[tc][b];
    const int*    __restrict__ off = g_off[tc][b];

    const int h = min(max((int)((qz - ZLO) * INVW), 0), S - 1);

    float best = CUDART_INF_F;               // partial: min(t^2 - 2 q.t)

    auto scan = [&](int s) {
        int j = off[s];
        const int e = off[s + 1];
        for (; j + 1 < e; j += 2) {          // 2-way for MLP
            const float4 t0 = T[j], t1 = T[j + 1];
            float d0 = fmaf(qz, t0.z, t0.w);
            float d1 = fmaf(qz, t1.z, t1.w);
            d0 = fmaf(qy, t0.y, d0);
            d1 = fmaf(qy, t1.y, d1);
            d0 = fmaf(qx, t0.x, d0);
            d1 = fmaf(qx, t1.x, d1);
            best = fminf(best, fminf(d0, d1));
        }
        if (j < e) {
            const float4 t0 = T[j];
            float d0 = fmaf(qz, t0.z, t0.w);
            d0 = fmaf(qy, t0.y, d0);
            d0 = fmaf(qx, t0.x, d0);
            best = fminf(best, d0);
        }
    };

    float btrue = CUDART_INF_F;
    bool  done  = false;
    int   k     = 0;
    while (true) {
        if (!done) {
            if (k == 0) {
                scan(h);                     // home strip, gap 0
            } else {
                const int slo = h - k, shi = h + k;
                if (slo >= 0) {
                    const float g = qz - (ZLO + (float)(slo + 1) * W);
                    if (g * g < btrue) scan(slo);
                }
                if (shi < S) {
                    const float g = (ZLO + (float)shi * W) - qz;
                    if (g * g < btrue) scan(shi);
                }
            }
            btrue = qn2 + best;
            const int nlo = h - k - 1, nhi = h + k + 1;
            const float glo = qz - (ZLO + (float)(nlo + 1) * W);
            const float ghi = (ZLO + (float)nhi * W) - qz;
            done = ((nlo < 0)  || (glo * glo >= btrue)) &&
                   ((nhi >= S) || (ghi * ghi >= btrue));
        }
        if (__all_sync(0xffffffffu, done)) break;
        k++;
    }

    const float d2 = qn2 + best;             // exact min squared distance

    float v0 = 0.f, v1 = 0.f, v2 = 0.f, v3 = 0.f;
    if (pass == 0) {
        v0 = d2;                             // chamfer row term
        v1 = sqrtf(fmaxf(d2, 0.f));          // EMD term
        v3 = unc[b * N + qi];                // uncertainty (order-free sum)
    } else {
        v2 = d2;                             // chamfer col term
    }

    // warp reduce
#pragma unroll
    for (int o = 16; o > 0; o >>= 1) {
        v0 += __shfl_down_sync(0xffffffffu, v0, o);
        v1 += __shfl_down_sync(0xffffffffu, v1, o);
        v2 += __shfl_down_sync(0xffffffffu, v2, o);
        v3 += __shfl_down_sync(0xffffffffu, v3, o);
    }
    __shared__ float red[4][QT / 32];
    if ((tid & 31) == 0) {
        const int w = tid >> 5;
        red[0][w] = v0; red[1][w] = v1; red[2][w] = v2; red[3][w] = v3;
    }
    __syncthreads();

    if (tid == 0) {
        float a0 = 0.f, a1 = 0.f, a2 = 0.f, a3 = 0.f;
#pragma unroll
        for (int w = 0; w < QT / 32; w++) {
            a0 += red[0][w]; a1 += red[1][w]; a2 += red[2][w]; a3 += red[3][w];
        }
        atomicAdd(&g_acc[0], a0);
        atomicAdd(&g_acc[1], a1);
        atomicAdd(&g_acc[2], a2);
        atomicAdd(&g_acc[3], a3);

        __threadfence();
        const unsigned t = atomicAdd(&g_tick, 1u);
        if (t == (unsigned)(TOTALB - 1)) {   // last block finalizes
            __threadfence();
            const float inv = 1.0f / (float)(B * N);
            const float chamfer = (g_acc[0] + g_acc[2]) * inv;
            const float emd     = g_acc[1] * inv;
            const float u       = g_acc[3] * inv;
            out[0] = chamfer * 1.0f + emd * 0.5f + u * 0.01f;
            g_tick = 0u;                     // reset for next graph replay
        }
    }
}

// ---------------------------------------------------------------------------
extern "C" void kernel_launch(void* const* d_in, const int* in_sizes, int n_in,
                              void* d_out, int out_size)
{
    const float* pred = (const float*)d_in[0];   // [B, N, 3]
    const float* targ = (const float*)d_in[1];   // [B, M, 3]
    const float* unc  = (const float*)d_in[2];   // [B, N]
    float* out = (float*)d_out;

    dim3 bgrid(2, B);                            // 16 blocks
    bucket_kernel<<<bgrid, 256>>>(pred, targ);

    dim3 sgrid(QBLK, B, 2);                      // 512 blocks x 128
    search_kernel<<<sgrid, QT>>>(unc, out);
}

// round 8
// speedup vs baseline: 3.0161x; 3.0161x over previous
#include <cuda_runtime.h>
#include <math_constants.h>

// Problem constants (fixed by reference)
constexpr int B = 8;
constexpr int N = 4096;          // == M

// z-strip sort grid
constexpr int   S    = 200;
constexpr float ZLO  = -5.0f;
constexpr float W    = 0.05f;
constexpr float INVW = 20.0f;

constexpr int CHK    = 32;               // target chunks per cloud
constexpr int CSZ    = N / CHK;          // 128 points per chunk
constexpr int QT     = 128;              // queries (=threads) per search block
constexpr int QBLK   = N / QT;           // 32 query blocks per (pass,b)
constexpr int TOTALB = QBLK * B * 2;     // 512 search blocks

// Scratch (no allocations allowed)
// g_pts[c][b][i] = (-2x, -2y, -2z, x^2+y^2+z^2), z-sorted (strip granularity)
__device__ float4   g_pts[2][B][N];
// g_cb[c][b][k] = (zmin_k, zmax_k, lbound_k = min zmin[k..], ubound_k = max zmax[..k])
__device__ float4   g_cb[2][B][CHK];
__device__ float    g_acc[4];            // rowmin-sum, sqrt-sum, colmin-sum, unc-sum
__device__ unsigned g_tick;

// ---------------------------------------------------------------------------
// Bucket kernel: grid (2, B), block 256. Strip histogram + scatter (z-sort at
// strip granularity), then per-chunk z bounds + monotone prefix/suffix bounds.
// ---------------------------------------------------------------------------
__global__ void __launch_bounds__(256)
bucket_kernel(const float* __restrict__ pred, const float* __restrict__ targ)
{
    __shared__ int   cnt[S];
    __shared__ int   start[S];
    __shared__ int   cur[S];
    __shared__ float czmin[CHK], czmax[CHK];
    const int c = blockIdx.x, b = blockIdx.y, tid = threadIdx.x;
    const float* src = (c == 0 ? pred : targ) + (size_t)b * N * 3;

    if (c == 0 && b == 0) {
        if (tid < 4) g_acc[tid] = 0.f;
        if (tid == 4) g_tick = 0u;
    }

    for (int s = tid; s < S; s += 256) { cnt[s] = 0; cur[s] = 0; }
    __syncthreads();

    for (int i = tid; i < N; i += 256) {
        const float z = src[i * 3 + 2];
        const int s = min(max((int)((z - ZLO) * INVW), 0), S - 1);
        atomicAdd(&cnt[s], 1);
    }
    __syncthreads();

    if (tid == 0) {
        int acc = 0;
        for (int s = 0; s < S; s++) { start[s] = acc; acc += cnt[s]; }
    }
    __syncthreads();

    for (int i = tid; i < N; i += 256) {
        const float x = src[i * 3 + 0];
        const float y = src[i * 3 + 1];
        const float z = src[i * 3 + 2];
        const int s = min(max((int)((z - ZLO) * INVW), 0), S - 1);
        const int pos = start[s] + atomicAdd(&cur[s], 1);
        g_pts[c][b][pos] = make_float4(-2.f * x, -2.f * y, -2.f * z,
                                       x * x + y * y + z * z);
    }
    __syncthreads();

    // per-chunk z min/max: 8 warps x 4 chunks, 4 points per lane
    {
        const int w = tid >> 5, lane = tid & 31;
        for (int q = 0; q < 4; q++) {
            const int ch = w * 4 + q;
            float zmn = CUDART_INF_F, zmx = -CUDART_INF_F;
#pragma unroll
            for (int i = 0; i < 4; i++) {
                const float z = -0.5f * g_pts[c][b][ch * CSZ + lane + 32 * i].z;
                zmn = fminf(zmn, z);
                zmx = fmaxf(zmx, z);
            }
#pragma unroll
            for (int o = 16; o > 0; o >>= 1) {
                zmn = fminf(zmn, __shfl_down_sync(0xffffffffu, zmn, o));
                zmx = fmaxf(zmx, __shfl_down_sync(0xffffffffu, zmx, o));
            }
            if (lane == 0) { czmin[ch] = zmn; czmax[ch] = zmx; }
        }
    }
    __syncthreads();

    if (tid == 0) {                       // monotone bounds (exactness guard)
        float ub = -CUDART_INF_F;
        float lb[CHK + 1];
        lb[CHK] = CUDART_INF_F;
        for (int k = CHK - 1; k >= 0; k--) lb[k] = fminf(lb[k + 1], czmin[k]);
        for (int k = 0; k < CHK; k++) {
            ub = fmaxf(ub, czmax[k]);
            g_cb[c][b][k] = make_float4(czmin[k], czmax[k], lb[k], ub);
        }
    }
}

// ---------------------------------------------------------------------------
// Search kernel: grid (QBLK, B, 2), block 128. pass 0: queries=pred (row-min,
// EMD, unc); pass 1: queries=targ (col-min). Block walks target chunks
// outward from a shared home; each chunk staged in smem, dense FFMA eval.
// Per-thread chunk prune via true chunk bounds; block exit via monotone
// bounds + __syncthreads_and -> exact.
// ---------------------------------------------------------------------------
__global__ void __launch_bounds__(QT)
search_kernel(const float* __restrict__ unc, float* __restrict__ out)
{
    __shared__ float4 sc[CSZ];           // staged target chunk
    __shared__ float4 bounds[CHK];       // (zmin, zmax, lbound, ubound)
    __shared__ int    sH;

    const int tid  = threadIdx.x;
    const int b    = blockIdx.y;
    const int pass = blockIdx.z;
    const int qc   = pass, tc = 1 - pass;
    const int qi   = blockIdx.x * QT + tid;   // sorted-order query index

    const float4* __restrict__ T = g_pts[tc][b];

    if (tid < CHK) bounds[tid] = g_cb[tc][b][tid];

    const float4 Q  = g_pts[qc][b][qi];
    const float qx  = -0.5f * Q.x;
    const float qy  = -0.5f * Q.y;
    const float qz  = -0.5f * Q.z;
    const float qn2 = Q.w;
    __syncthreads();

    // home chunk = last chunk with zmin <= qz (thread 64's choice shared)
    int h = 0;
#pragma unroll
    for (int k2 = 1; k2 < CHK; k2++) if (bounds[k2].x <= qz) h = k2;
    if (tid == QT / 2) sH = h;
    __syncthreads();
    const int H = sH;

    float best  = CUDART_INF_F;          // partial: min(t^2 - 2 q.t)
    float btrue = CUDART_INF_F;          // qn2 + best
    bool  done  = false;

    for (int k = 0; k <= CHK; k++) {
        const int clo = H - k, chi = H + k;
#pragma unroll
        for (int side = 0; side < 2; side++) {
            const int ch = side ? chi : clo;
            if (ch < 0 || ch >= CHK || (side && k == 0)) continue;

            // stage chunk
            __syncthreads();
            sc[tid] = T[ch * CSZ + tid];
            __syncthreads();

            if (!done) {
                const float4 cb = bounds[ch];
                const float gap = fmaxf(fmaxf(cb.x - qz, qz - cb.y), 0.f);
                if (gap * gap < btrue) {
#pragma unroll 4
                    for (int j = 0; j < CSZ; j++) {
                        const float4 t = sc[j];
                        float d = fmaf(qz, t.z, t.w);
                        d = fmaf(qy, t.y, d);
                        d = fmaf(qx, t.x, d);
                        best = fminf(best, d);
                    }
                    btrue = qn2 + best;
                }
            }
        }
        // exit check with monotone bounds (conservative, exact)
        if (!done) {
            const int nlo = H - k - 1, nhi = H + k + 1;
            const float glo = (nlo >= 0)
                ? fmaxf(qz - bounds[nlo].w, 0.f) : CUDART_INF_F;  // ubound
            const float ghi = (nhi < CHK)
                ? fmaxf(bounds[nhi].z - qz, 0.f) : CUDART_INF_F;  // lbound
            done = (glo * glo >= btrue) && (ghi * ghi >= btrue);
        }
        if (__syncthreads_and(done)) break;
    }

    const float d2 = qn2 + best;         // exact min squared distance

    float v0 = 0.f, v1 = 0.f, v2 = 0.f, v3 = 0.f;
    if (pass == 0) {
        v0 = d2;                          // chamfer row term
        v1 = sqrtf(fmaxf(d2, 0.f));       // EMD term
        v3 = unc[b * N + qi];             // uncertainty (order-free sum)
    } else {
        v2 = d2;                          // chamfer col term
    }

#pragma unroll
    for (int o = 16; o > 0; o >>= 1) {
        v0 += __shfl_down_sync(0xffffffffu, v0, o);
        v1 += __shfl_down_sync(0xffffffffu, v1, o);
        v2 += __shfl_down_sync(0xffffffffu, v2, o);
        v3 += __shfl_down_sync(0xffffffffu, v3, o);
    }
    __shared__ float red[4][QT / 32];
    if ((tid & 31) == 0) {
        const int w = tid >> 5;
        red[0][w] = v0; red[1][w] = v1; red[2][w] = v2; red[3][w] = v3;
    }
    __syncthreads();

    if (tid == 0) {
        float a0 = 0.f, a1 = 0.f, a2 = 0.f, a3 = 0.f;
#pragma unroll
        for (int w = 0; w < QT / 32; w++) {
            a0 += red[0][w]; a1 += red[1][w]; a2 += red[2][w]; a3 += red[3][w];
        }
        atomicAdd(&g_acc[0], a0);
        atomicAdd(&g_acc[1], a1);
        atomicAdd(&g_acc[2], a2);
        atomicAdd(&g_acc[3], a3);

        __threadfence();
        const unsigned t = atomicAdd(&g_tick, 1u);
        if (t == (unsigned)(TOTALB - 1)) {    // last block finalizes
            __threadfence();
            const float inv = 1.0f / (float)(B * N);
            const float chamfer = (g_acc[0] + g_acc[2]) * inv;
            const float emd     = g_acc[1] * inv;
            const float u       = g_acc[3] * inv;
            out[0] = chamfer * 1.0f + emd * 0.5f + u * 0.01f;
            g_tick = 0u;                      // reset for next graph replay
        }
    }
}

// ---------------------------------------------------------------------------
extern "C" void kernel_launch(void* const* d_in, const int* in_sizes, int n_in,
                              void* d_out, int out_size)
{
    const float* pred = (const float*)d_in[0];   // [B, N, 3]
    const float* targ = (const float*)d_in[1];   // [B, M, 3]
    const float* unc  = (const float*)d_in[2];   // [B, N]
    float* out = (float*)d_out;

    dim3 bgrid(2, B);                            // 16 blocks
    bucket_kernel<<<bgrid, 256>>>(pred, targ);

    dim3 sgrid(QBLK, B, 2);                      // 512 blocks x 128
    search_kernel<<<sgrid, QT>>>(unc, out);
}